// round 15
// baseline (speedup 1.0000x reference)
#include <cuda_runtime.h>
#include <cuda_fp16.h>
#include <math_constants.h>

// ---------------------------------------------------------------------------
// Problem constants
// ---------------------------------------------------------------------------
#define NN 8192
#define CC 256
#define TM 128                  // CTA rows
#define TNT 128                 // CTA col-tile width
#define NSPLIT 4
#define CPS (NN / NSPLIT)       // 2048 cols per CTA
#define NTILE (CPS / TNT)       // 16 col tiles
#define KCH 64                  // k per chunk
#define NCHUNKS (NTILE * 4)     // 64 chunk steps
#define NTHREADS 128            // 4 warps, 2x2 grid of 64x64 warp tiles
#define INV_T 14.285714285714285714f
#define LN2 0.6931471805599453f
// sqrt(INV_T * log2(e)) folded into fp16 operands: acc = logit * log2(e)
#define SCALE 4.5398160052f

// SMEM layout (dynamic)
#define A_STRIDE 528            // 256 halves + 8 pad
#define B_STRIDE 144            // 64 halves + 8 pad
#define SA 0
#define SA_BYTES (TM * A_STRIDE)            // 67584
#define SB (SA + SA_BYTES)
#define SB_STAGE (TNT * B_STRIDE)           // 18432
#define SRED_M (SB + 2 * SB_STAGE)          // 104448
#define SRED_S (SRED_M + TM * 2 * 4)        // +1024
#define SM_TOTAL (SRED_S + TM * 2 * 4)      // 106496  (x2 CTAs = 212992 < 228KB)

typedef unsigned int u32;

// ---------------------------------------------------------------------------
// Device globals (no allocation allowed)
// ---------------------------------------------------------------------------
__device__ __align__(16) __half g_kh[NN * CC];
__device__ float g_pm[NN * NSPLIT];
__device__ float g_ps[NN * NSPLIT];
__device__ float g_pos[NN];
__device__ float g_part[32];
__device__ unsigned int g_ticket;   // zero-initialized; reset by last block

// ---------------------------------------------------------------------------
// PTX helpers (base ISA only; must compile for compute_103 non-'a')
// ---------------------------------------------------------------------------
__device__ __forceinline__ u32 smem_u32(const void* p) {
    u32 a;
    asm("{ .reg .u64 t; cvta.to.shared.u64 t, %1; cvt.u32.u64 %0, t; }" : "=r"(a) : "l"(p));
    return a;
}
__device__ __forceinline__ void cp_async16(u32 dst, const void* src) {
    asm volatile("cp.async.cg.shared.global [%0], [%1], 16;" :: "r"(dst), "l"(src));
}
__device__ __forceinline__ void cp_commit() {
    asm volatile("cp.async.commit_group;" ::: "memory");
}
__device__ __forceinline__ void cp_wait0() {
    asm volatile("cp.async.wait_group 0;" ::: "memory");
}
__device__ __forceinline__ void ldsm_x4(u32& r0, u32& r1, u32& r2, u32& r3, u32 addr) {
    asm volatile("ldmatrix.sync.aligned.m8n8.x4.shared.b16 {%0,%1,%2,%3}, [%4];"
                 : "=r"(r0), "=r"(r1), "=r"(r2), "=r"(r3) : "r"(addr));
}
// fp16-accumulator HMMA: D halves d0={rows r}, d1={rows r+8}
__device__ __forceinline__ void mma16816_f16(u32& d0, u32& d1,
                                             u32 a0, u32 a1, u32 a2, u32 a3,
                                             u32 b0, u32 b1) {
    asm volatile("mma.sync.aligned.m16n8k16.row.col.f16.f16.f16.f16 "
                 "{%0,%1}, {%2,%3,%4,%5}, {%6,%7}, {%0,%1};"
                 : "+r"(d0), "+r"(d1)
                 : "r"(a0), "r"(a1), "r"(a2), "r"(a3), "r"(b0), "r"(b1));
}

// ---------------------------------------------------------------------------
// Convert K only: pure elementwise fp32 -> scaled fp16.
// One thread = 8 consecutive elements (2 x float4 LDG -> 1 x uint4 STG).
// grid 1024 x 256 = 262K threads: DRAM-roofline, not latency-bound.
// ---------------------------------------------------------------------------
__global__ void convert_k_kernel(const float* __restrict__ k) {
    const int i = blockIdx.x * blockDim.x + threadIdx.x;   // < NN*CC/8
    const float4 v0 = ((const float4*)k)[2 * i + 0];
    const float4 v1 = ((const float4*)k)[2 * i + 1];
    uint4 o;
    __half2 h;
    h = __floats2half2_rn(v0.x * SCALE, v0.y * SCALE); o.x = *(u32*)&h;
    h = __floats2half2_rn(v0.z * SCALE, v0.w * SCALE); o.y = *(u32*)&h;
    h = __floats2half2_rn(v1.x * SCALE, v1.y * SCALE); o.z = *(u32*)&h;
    h = __floats2half2_rn(v1.z * SCALE, v1.w * SCALE); o.w = *(u32*)&h;
    ((uint4*)g_kh)[i] = o;
}

// ---------------------------------------------------------------------------
// Main: HMMA fp16 GEMM (fp16 acc, 2x2 grid of 64x64 warp tiles) + online LSE.
// A converted fp32->fp16 in the prologue; pos extracted from the diagonal
// tile's accumulators (no separate q pass needed).
// grid = (NSPLIT=4, 64) = 256 CTAs, 128 threads, 2 CTAs/SM (8 warps/SM).
// ---------------------------------------------------------------------------
extern __shared__ char smem[];

__global__ __launch_bounds__(NTHREADS, 2)
void sim_lse_hmma_kernel(const float* __restrict__ qf) {
    const int tid = threadIdx.x;
    const int wid = tid >> 5;
    const int lane = tid & 31;
    const int warp_m = wid >> 1;            // 0..1 (64 rows each)
    const int warp_n = wid & 1;             // 0..1 (64 cols each)
    const int split = blockIdx.x;
    const int rowBase = blockIdx.y * TM;
    const int colBase0 = split * CPS;

    // diagonal bookkeeping
    const bool isDiagCTA = (split == (blockIdx.y >> 4));
    const int diagTile = blockIdx.y & 15;
    const int la = lane >> 2, lb = lane & 3;
    const bool dv0 = (la == 2 * lb);
    const bool dv1 = (la == 2 * lb + 1);
    const bool diagValid = dv0 || dv1;

    const u32 sbase = smem_u32(smem);

    // ---- B chunk 0 via cp.async (overlaps the A conversion below) ----
#pragma unroll
    for (int i = 0; i < 8; i++) {
        const int f = tid + i * NTHREADS;
        const int r = f >> 3;
        const int g = f & 7;
        cp_async16(sbase + SB + r * B_STRIDE + g * 16,
                   g_kh + (size_t)(colBase0 + r) * CC + g * 8);
    }
    cp_commit();

    // ---- A prologue: load fp32 q rows, convert to scaled fp16, STS ----
#pragma unroll 4
    for (int i = 0; i < 32; i++) {
        const int f = tid + i * NTHREADS;
        const int r = f >> 5;               // row 0..127
        const int g16 = f & 31;             // 16B half-segment 0..31
        const float4* src = (const float4*)(qf + (size_t)(rowBase + r) * CC + g16 * 8);
        const float4 v0 = src[0];
        const float4 v1 = src[1];
        uint4 o;
        __half2 h;
        h = __floats2half2_rn(v0.x * SCALE, v0.y * SCALE); o.x = *(u32*)&h;
        h = __floats2half2_rn(v0.z * SCALE, v0.w * SCALE); o.y = *(u32*)&h;
        h = __floats2half2_rn(v1.x * SCALE, v1.y * SCALE); o.z = *(u32*)&h;
        h = __floats2half2_rn(v1.z * SCALE, v1.w * SCALE); o.w = *(u32*)&h;
        *(uint4*)(smem + SA + r * A_STRIDE + g16 * 16) = o;
    }

    cp_wait0();
    __syncthreads();

    // fp16 accumulators: [mt 0..3][no 0..7][h 0..1] packed half2
    u32 acc[4][8][2];
#pragma unroll
    for (int mt = 0; mt < 4; mt++)
#pragma unroll
        for (int no = 0; no < 8; no++) { acc[mt][no][0] = 0u; acc[mt][no][1] = 0u; }

    __half2 rmv[4];
#pragma unroll
    for (int i = 0; i < 4; i++) rmv[i] = __floats2half2_rn(-CUDART_INF_F, -CUDART_INF_F);
    float rs[8];
#pragma unroll
    for (int s = 0; s < 8; s++) rs[s] = 0.0f;

    const u32 a_lane = (u32)((warp_m * 64 + (lane & 15)) * A_STRIDE + (lane >> 4) * 16);
    const u32 b_lane = (u32)((warp_n * 64 + (lane >> 4) * 8 + (lane & 7)) * B_STRIDE
                             + ((lane >> 3) & 1) * 16);

    for (int t = 0; t < NCHUNKS; t++) {
        const u32 bs = sbase + SB + (t & 1) * SB_STAGE;

        if (t + 1 < NCHUNKS) {
            const int nt = (t + 1) >> 2;
            const int nc = (t + 1) & 3;
            const int colBase = colBase0 + nt * TNT;
            const u32 bd = sbase + SB + ((t + 1) & 1) * SB_STAGE;
#pragma unroll
            for (int i = 0; i < 8; i++) {
                const int f = tid + i * NTHREADS;
                const int r = f >> 3;
                const int g = f & 7;
                cp_async16(bd + r * B_STRIDE + g * 16,
                           g_kh + (size_t)(colBase + r) * CC + nc * KCH + g * 8);
            }
            cp_commit();
        }

        const int kc = (t & 3) * KCH;
#pragma unroll
        for (int ks = 0; ks < 4; ks++) {
            u32 b[4][4];
#pragma unroll
            for (int nt = 0; nt < 4; nt++)
                ldsm_x4(b[nt][0], b[nt][1], b[nt][2], b[nt][3],
                        bs + b_lane + (u32)(nt * 16 * B_STRIDE + ks * 32));
#pragma unroll
            for (int half = 0; half < 2; half++) {
                u32 a[2][4];
#pragma unroll
                for (int m2 = 0; m2 < 2; m2++)
                    ldsm_x4(a[m2][0], a[m2][1], a[m2][2], a[m2][3],
                            sbase + SA + a_lane
                            + (u32)((half * 2 + m2) * 16 * A_STRIDE + (kc + ks * 16) * 2));
#pragma unroll
                for (int m2 = 0; m2 < 2; m2++)
#pragma unroll
                    for (int no = 0; no < 8; no++) {
                        const int bt = no >> 1, pr = no & 1;
                        mma16816_f16(acc[half * 2 + m2][no][0], acc[half * 2 + m2][no][1],
                                     a[m2][0], a[m2][1], a[m2][2], a[m2][3],
                                     b[bt][pr * 2], b[bt][pr * 2 + 1]);
                    }
            }
        }

        // ---- tile finished: pos extraction (diag tile) + fp16 online LSE ----
        if ((t & 3) == 3) {
            if (isDiagCTA && (t >> 2) == diagTile && warp_m == warp_n && diagValid) {
#pragma unroll
                for (int mt = 0; mt < 4; mt++)
#pragma unroll
                    for (int h = 0; h < 2; h++) {
                        const u32 w = acc[mt][2 * mt + h][h];
                        const __half2 w2 = *reinterpret_cast<const __half2*>(&w);
                        const __half v = dv1 ? __high2half(w2) : __low2half(w2);
                        const int R = rowBase + warp_m * 64 + mt * 16 + h * 8 + la;
                        g_pos[R] = __half2float(v) * LN2;
                    }
            }
#pragma unroll
            for (int mt = 0; mt < 4; mt++) {
#pragma unroll
                for (int h = 0; h < 2; h++) {
                    const int s = mt * 2 + h;
                    __half2 x2[8];
#pragma unroll
                    for (int no = 0; no < 8; no++)
                        x2[no] = *reinterpret_cast<__half2*>(&acc[mt][no][h]);
                    __half2 m2v = __hmax2(__hmax2(__hmax2(x2[0], x2[1]), __hmax2(x2[2], x2[3])),
                                          __hmax2(__hmax2(x2[4], x2[5]), __hmax2(x2[6], x2[7])));
                    const __half mloc = __hmax(__low2half(m2v), __high2half(m2v));
                    const __half rmold = (h == 0) ? __low2half(rmv[mt]) : __high2half(rmv[mt]);
                    const __half mn = __hmax(rmold, mloc);           // exact fp16 max
                    const __half2 mn2 = __half2half2(mn);
                    __half2 s2 = h2exp2(__hsub2(x2[0], mn2));
                    __half2 s2b = h2exp2(__hsub2(x2[1], mn2));
#pragma unroll
                    for (int no = 2; no < 8; no += 2) {
                        s2 = __hadd2(s2, h2exp2(__hsub2(x2[no], mn2)));
                        s2b = __hadd2(s2b, h2exp2(__hsub2(x2[no + 1], mn2)));
                    }
                    s2 = __hadd2(s2, s2b);
                    const float bsm = __half2float(__low2half(s2)) + __half2float(__high2half(s2));
                    rs[s] = rs[s] * exp2f(__half2float(rmold) - __half2float(mn)) + bsm;
                    rmv[mt] = (h == 0) ? __halves2half2(mn, __high2half(rmv[mt]))
                                       : __halves2half2(__low2half(rmv[mt]), mn);
                }
#pragma unroll
                for (int no = 0; no < 8; no++) { acc[mt][no][0] = 0u; acc[mt][no][1] = 0u; }
            }
        }

        cp_wait0();
        __syncthreads();
    }

    // ---- unpack rm to fp32, merge across the 4 lanes sharing each row ----
    float rmf[8];
#pragma unroll
    for (int mt = 0; mt < 4; mt++) {
        rmf[mt * 2 + 0] = __half2float(__low2half(rmv[mt]));
        rmf[mt * 2 + 1] = __half2float(__high2half(rmv[mt]));
    }
#pragma unroll
    for (int s = 0; s < 8; s++) {
#pragma unroll
        for (int off = 1; off <= 2; off <<= 1) {
            const float om = __shfl_xor_sync(0xFFFFFFFFu, rmf[s], off);
            const float os = __shfl_xor_sync(0xFFFFFFFFu, rs[s], off);
            const float nm = fmaxf(rmf[s], om);
            rs[s] = rs[s] * exp2f(rmf[s] - nm) + os * exp2f(om - nm);
            rmf[s] = nm;
        }
    }

    // ---- cross-warp reduce (2 warp_n groups) + store split partials ----
    float* redm = (float*)(smem + SRED_M);
    float* reds = (float*)(smem + SRED_S);
    if ((lane & 3) == 0) {
#pragma unroll
        for (int mt = 0; mt < 4; mt++)
#pragma unroll
            for (int h = 0; h < 2; h++) {
                const int row = warp_m * 64 + mt * 16 + h * 8 + (lane >> 2);
                redm[row * 2 + warp_n] = rmf[mt * 2 + h];
                reds[row * 2 + warp_n] = rs[mt * 2 + h];
            }
    }
    __syncthreads();
    if (tid < TM) {
        const float m0 = redm[tid * 2], m1 = redm[tid * 2 + 1];
        const float mg = fmaxf(m0, m1);
        const float sg = reds[tid * 2] * exp2f(m0 - mg) + reds[tid * 2 + 1] * exp2f(m1 - mg);
        g_pm[(rowBase + tid) * NSPLIT + split] = mg;
        g_ps[(rowBase + tid) * NSPLIT + split] = sg;
    }
}

// ---------------------------------------------------------------------------
// Combine (single launch): 32 blocks reduce 256 rows each; the last block to
// finish sums the 32 partials in fixed order (deterministic) and writes out.
// ---------------------------------------------------------------------------
__global__ void combine_kernel(float* __restrict__ out) {
    __shared__ float red[256];
    __shared__ bool amLast;
    const int r = blockIdx.x * 256 + threadIdx.x;
    const float4 pm = *(const float4*)(g_pm + r * NSPLIT);
    const float4 ps = *(const float4*)(g_ps + r * NSPLIT);
    const float mg = fmaxf(fmaxf(pm.x, pm.y), fmaxf(pm.z, pm.w));
    const float sg = ps.x * exp2f(pm.x - mg) + ps.y * exp2f(pm.y - mg)
                   + ps.z * exp2f(pm.z - mg) + ps.w * exp2f(pm.w - mg);
    red[threadIdx.x] = LN2 * (mg + log2f(sg)) - g_pos[r];
    __syncthreads();
    for (int o = 128; o; o >>= 1) {
        if (threadIdx.x < o) red[threadIdx.x] += red[threadIdx.x + o];
        __syncthreads();
    }
    if (threadIdx.x == 0) {
        g_part[blockIdx.x] = red[0];
        __threadfence();
        const unsigned int t = atomicAdd(&g_ticket, 1u);
        amLast = (t == 31u);
    }
    __syncthreads();
    if (amLast && threadIdx.x == 0) {
        float tot = 0.0f;
#pragma unroll
        for (int i = 0; i < 32; i++) tot += g_part[i];
        out[0] = tot / (float)NN;
        g_ticket = 0u;   // reset for next graph replay
    }
}

// ---------------------------------------------------------------------------
extern "C" void kernel_launch(void* const* d_in, const int* in_sizes, int n_in,
                              void* d_out, int out_size) {
    const float* q = (const float*)d_in[0];
    const float* k = (const float*)d_in[1];
    float* out = (float*)d_out;

    cudaFuncSetAttribute(sim_lse_hmma_kernel,
                         cudaFuncAttributeMaxDynamicSharedMemorySize, SM_TOTAL);

    convert_k_kernel<<<NN * CC / 8 / 256, 256>>>(k);   // elementwise, 1024 blocks
    dim3 grid(NSPLIT, NN / TM);
    sim_lse_hmma_kernel<<<grid, NTHREADS, SM_TOTAL>>>(q);
    combine_kernel<<<32, 256>>>(out);
}

// round 16
// speedup vs baseline: 1.0117x; 1.0117x over previous
#include <cuda_runtime.h>
#include <cuda_fp16.h>
#include <math_constants.h>

// ---------------------------------------------------------------------------
// Problem constants
// ---------------------------------------------------------------------------
#define NN 8192
#define CC 256
#define TM 128                  // CTA rows
#define TNT 128                 // CTA col-tile width
#define NSPLIT 4
#define CPS (NN / NSPLIT)       // 2048 cols per CTA
#define NTILE (CPS / TNT)       // 16 col tiles
#define KCH 64                  // k per chunk
#define NCHUNKS (NTILE * 4)     // 64 chunk steps
#define NTHREADS 128            // 4 warps, 2x2 grid of 64x64 warp tiles
#define INV_T 14.285714285714285714f
#define LN2 0.6931471805599453f
// sqrt(INV_T * log2(e)) folded into fp16 operands: acc = logit * log2(e)
#define SCALE 4.5398160052f

// SMEM layout (dynamic)
#define A_STRIDE 528            // 256 halves + 8 pad
#define B_STRIDE 144            // 64 halves + 8 pad
#define SA 0
#define SA_BYTES (TM * A_STRIDE)            // 67584
#define SB (SA + SA_BYTES)
#define SB_STAGE (TNT * B_STRIDE)           // 18432
#define SRED_M (SB + 2 * SB_STAGE)          // 104448
#define SRED_S (SRED_M + TM * 2 * 4)        // +1024
#define SM_TOTAL (SRED_S + TM * 2 * 4)      // 106496  (x2 CTAs = 212992 < 228KB)

typedef unsigned int u32;

// ---------------------------------------------------------------------------
// Device globals (no allocation allowed)
// ---------------------------------------------------------------------------
__device__ __align__(16) __half g_kh[NN * CC];
__device__ float g_pm[NN * NSPLIT];
__device__ float g_ps[NN * NSPLIT];
__device__ float g_pos[NN];
__device__ float g_part[32];
__device__ unsigned int g_ticket;   // zero-initialized; reset by last block

// ---------------------------------------------------------------------------
// PTX helpers (base ISA only; must compile for compute_103 non-'a')
// ---------------------------------------------------------------------------
__device__ __forceinline__ u32 smem_u32(const void* p) {
    u32 a;
    asm("{ .reg .u64 t; cvta.to.shared.u64 t, %1; cvt.u32.u64 %0, t; }" : "=r"(a) : "l"(p));
    return a;
}
__device__ __forceinline__ void cp_async16(u32 dst, const void* src) {
    asm volatile("cp.async.cg.shared.global [%0], [%1], 16;" :: "r"(dst), "l"(src));
}
__device__ __forceinline__ void cp_commit() {
    asm volatile("cp.async.commit_group;" ::: "memory");
}
__device__ __forceinline__ void cp_wait0() {
    asm volatile("cp.async.wait_group 0;" ::: "memory");
}
__device__ __forceinline__ void ldsm_x4(u32& r0, u32& r1, u32& r2, u32& r3, u32 addr) {
    asm volatile("ldmatrix.sync.aligned.m8n8.x4.shared.b16 {%0,%1,%2,%3}, [%4];"
                 : "=r"(r0), "=r"(r1), "=r"(r2), "=r"(r3) : "r"(addr));
}
// fp16-accumulator HMMA: D halves d0={rows r}, d1={rows r+8}
__device__ __forceinline__ void mma16816_f16(u32& d0, u32& d1,
                                             u32 a0, u32 a1, u32 a2, u32 a3,
                                             u32 b0, u32 b1) {
    asm volatile("mma.sync.aligned.m16n8k16.row.col.f16.f16.f16.f16 "
                 "{%0,%1}, {%2,%3,%4,%5}, {%6,%7}, {%0,%1};"
                 : "+r"(d0), "+r"(d1)
                 : "r"(a0), "r"(a1), "r"(a2), "r"(a3), "r"(b0), "r"(b1));
}
// PDL primitives (griddepcontrol.*, sm_90+ base PTX)
__device__ __forceinline__ void pdl_wait() {
    asm volatile("griddepcontrol.wait;" ::: "memory");
}
__device__ __forceinline__ void pdl_launch_dependents() {
    asm volatile("griddepcontrol.launch_dependents;" ::: "memory");
}

// ---------------------------------------------------------------------------
// Convert K only: pure elementwise fp32 -> scaled fp16, then release
// dependents early (PDL trigger).
// ---------------------------------------------------------------------------
__global__ void convert_k_kernel(const float* __restrict__ k) {
    const int i = blockIdx.x * blockDim.x + threadIdx.x;   // < NN*CC/8
    const float4 v0 = ((const float4*)k)[2 * i + 0];
    const float4 v1 = ((const float4*)k)[2 * i + 1];
    uint4 o;
    __half2 h;
    h = __floats2half2_rn(v0.x * SCALE, v0.y * SCALE); o.x = *(u32*)&h;
    h = __floats2half2_rn(v0.z * SCALE, v0.w * SCALE); o.y = *(u32*)&h;
    h = __floats2half2_rn(v1.x * SCALE, v1.y * SCALE); o.z = *(u32*)&h;
    h = __floats2half2_rn(v1.z * SCALE, v1.w * SCALE); o.w = *(u32*)&h;
    ((uint4*)g_kh)[i] = o;
    __syncthreads();            // block's stores issued before trigger
    pdl_launch_dependents();
}

// ---------------------------------------------------------------------------
// Main: HMMA fp16 GEMM (fp16 acc, 2x2 grid of 64x64 warp tiles) + online LSE.
// Launched with programmaticStreamSerialization: CTAs start under convert_k;
// A prologue (fp32 q -> fp16 smem) needs no g_kh; pdl_wait() gates the first
// B cp.async. pos extracted from the diagonal tile's accumulators.
// grid = (NSPLIT=4, 64) = 256 CTAs, 128 threads, 2 CTAs/SM.
// ---------------------------------------------------------------------------
extern __shared__ char smem[];

__global__ __launch_bounds__(NTHREADS, 2)
void sim_lse_hmma_kernel(const float* __restrict__ qf) {
    const int tid = threadIdx.x;
    const int wid = tid >> 5;
    const int lane = tid & 31;
    const int warp_m = wid >> 1;            // 0..1 (64 rows each)
    const int warp_n = wid & 1;             // 0..1 (64 cols each)
    const int split = blockIdx.x;
    const int rowBase = blockIdx.y * TM;
    const int colBase0 = split * CPS;

    // diagonal bookkeeping
    const bool isDiagCTA = (split == (blockIdx.y >> 4));
    const int diagTile = blockIdx.y & 15;
    const int la = lane >> 2, lb = lane & 3;
    const bool dv0 = (la == 2 * lb);
    const bool dv1 = (la == 2 * lb + 1);
    const bool diagValid = dv0 || dv1;

    const u32 sbase = smem_u32(smem);

    // ---- A prologue FIRST (independent of convert_k): q fp32 -> fp16 STS ----
#pragma unroll 4
    for (int i = 0; i < 32; i++) {
        const int f = tid + i * NTHREADS;
        const int r = f >> 5;               // row 0..127
        const int g16 = f & 31;             // 16B half-segment 0..31
        const float4* src = (const float4*)(qf + (size_t)(rowBase + r) * CC + g16 * 8);
        const float4 v0 = src[0];
        const float4 v1 = src[1];
        uint4 o;
        __half2 h;
        h = __floats2half2_rn(v0.x * SCALE, v0.y * SCALE); o.x = *(u32*)&h;
        h = __floats2half2_rn(v0.z * SCALE, v0.w * SCALE); o.y = *(u32*)&h;
        h = __floats2half2_rn(v1.x * SCALE, v1.y * SCALE); o.z = *(u32*)&h;
        h = __floats2half2_rn(v1.z * SCALE, v1.w * SCALE); o.w = *(u32*)&h;
        *(uint4*)(smem + SA + r * A_STRIDE + g16 * 16) = o;
    }

    // ---- wait for convert_k's outputs, then B chunk 0 via cp.async ----
    pdl_wait();
#pragma unroll
    for (int i = 0; i < 8; i++) {
        const int f = tid + i * NTHREADS;
        const int r = f >> 3;
        const int g = f & 7;
        cp_async16(sbase + SB + r * B_STRIDE + g * 16,
                   g_kh + (size_t)(colBase0 + r) * CC + g * 8);
    }
    cp_commit();
    cp_wait0();
    __syncthreads();

    // fp16 accumulators: [mt 0..3][no 0..7][h 0..1] packed half2
    u32 acc[4][8][2];
#pragma unroll
    for (int mt = 0; mt < 4; mt++)
#pragma unroll
        for (int no = 0; no < 8; no++) { acc[mt][no][0] = 0u; acc[mt][no][1] = 0u; }

    __half2 rmv[4];
#pragma unroll
    for (int i = 0; i < 4; i++) rmv[i] = __floats2half2_rn(-CUDART_INF_F, -CUDART_INF_F);
    float rs[8];
#pragma unroll
    for (int s = 0; s < 8; s++) rs[s] = 0.0f;

    const u32 a_lane = (u32)((warp_m * 64 + (lane & 15)) * A_STRIDE + (lane >> 4) * 16);
    const u32 b_lane = (u32)((warp_n * 64 + (lane >> 4) * 8 + (lane & 7)) * B_STRIDE
                             + ((lane >> 3) & 1) * 16);

    for (int t = 0; t < NCHUNKS; t++) {
        const u32 bs = sbase + SB + (t & 1) * SB_STAGE;

        if (t + 1 < NCHUNKS) {
            const int nt = (t + 1) >> 2;
            const int nc = (t + 1) & 3;
            const int colBase = colBase0 + nt * TNT;
            const u32 bd = sbase + SB + ((t + 1) & 1) * SB_STAGE;
#pragma unroll
            for (int i = 0; i < 8; i++) {
                const int f = tid + i * NTHREADS;
                const int r = f >> 3;
                const int g = f & 7;
                cp_async16(bd + r * B_STRIDE + g * 16,
                           g_kh + (size_t)(colBase + r) * CC + nc * KCH + g * 8);
            }
            cp_commit();
        }

        const int kc = (t & 3) * KCH;
#pragma unroll
        for (int ks = 0; ks < 4; ks++) {
            u32 b[4][4];
#pragma unroll
            for (int nt = 0; nt < 4; nt++)
                ldsm_x4(b[nt][0], b[nt][1], b[nt][2], b[nt][3],
                        bs + b_lane + (u32)(nt * 16 * B_STRIDE + ks * 32));
#pragma unroll
            for (int half = 0; half < 2; half++) {
                u32 a[2][4];
#pragma unroll
                for (int m2 = 0; m2 < 2; m2++)
                    ldsm_x4(a[m2][0], a[m2][1], a[m2][2], a[m2][3],
                            sbase + SA + a_lane
                            + (u32)((half * 2 + m2) * 16 * A_STRIDE + (kc + ks * 16) * 2));
#pragma unroll
                for (int m2 = 0; m2 < 2; m2++)
#pragma unroll
                    for (int no = 0; no < 8; no++) {
                        const int bt = no >> 1, pr = no & 1;
                        mma16816_f16(acc[half * 2 + m2][no][0], acc[half * 2 + m2][no][1],
                                     a[m2][0], a[m2][1], a[m2][2], a[m2][3],
                                     b[bt][pr * 2], b[bt][pr * 2 + 1]);
                    }
            }
        }

        // ---- tile finished: pos extraction (diag tile) + fp16 online LSE ----
        if ((t & 3) == 3) {
            if (isDiagCTA && (t >> 2) == diagTile && warp_m == warp_n && diagValid) {
#pragma unroll
                for (int mt = 0; mt < 4; mt++)
#pragma unroll
                    for (int h = 0; h < 2; h++) {
                        const u32 w = acc[mt][2 * mt + h][h];
                        const __half2 w2 = *reinterpret_cast<const __half2*>(&w);
                        const __half v = dv1 ? __high2half(w2) : __low2half(w2);
                        const int R = rowBase + warp_m * 64 + mt * 16 + h * 8 + la;
                        g_pos[R] = __half2float(v) * LN2;
                    }
            }
#pragma unroll
            for (int mt = 0; mt < 4; mt++) {
#pragma unroll
                for (int h = 0; h < 2; h++) {
                    const int s = mt * 2 + h;
                    __half2 x2[8];
#pragma unroll
                    for (int no = 0; no < 8; no++)
                        x2[no] = *reinterpret_cast<__half2*>(&acc[mt][no][h]);
                    __half2 m2v = __hmax2(__hmax2(__hmax2(x2[0], x2[1]), __hmax2(x2[2], x2[3])),
                                          __hmax2(__hmax2(x2[4], x2[5]), __hmax2(x2[6], x2[7])));
                    const __half mloc = __hmax(__low2half(m2v), __high2half(m2v));
                    const __half rmold = (h == 0) ? __low2half(rmv[mt]) : __high2half(rmv[mt]);
                    const __half mn = __hmax(rmold, mloc);           // exact fp16 max
                    const __half2 mn2 = __half2half2(mn);
                    __half2 s2 = h2exp2(__hsub2(x2[0], mn2));
                    __half2 s2b = h2exp2(__hsub2(x2[1], mn2));
#pragma unroll
                    for (int no = 2; no < 8; no += 2) {
                        s2 = __hadd2(s2, h2exp2(__hsub2(x2[no], mn2)));
                        s2b = __hadd2(s2b, h2exp2(__hsub2(x2[no + 1], mn2)));
                    }
                    s2 = __hadd2(s2, s2b);
                    const float bsm = __half2float(__low2half(s2)) + __half2float(__high2half(s2));
                    rs[s] = rs[s] * exp2f(__half2float(rmold) - __half2float(mn)) + bsm;
                    rmv[mt] = (h == 0) ? __halves2half2(mn, __high2half(rmv[mt]))
                                       : __halves2half2(__low2half(rmv[mt]), mn);
                }
#pragma unroll
                for (int no = 0; no < 8; no++) { acc[mt][no][0] = 0u; acc[mt][no][1] = 0u; }
            }
        }

        cp_wait0();
        __syncthreads();
    }

    // ---- unpack rm to fp32, merge across the 4 lanes sharing each row ----
    float rmf[8];
#pragma unroll
    for (int mt = 0; mt < 4; mt++) {
        rmf[mt * 2 + 0] = __half2float(__low2half(rmv[mt]));
        rmf[mt * 2 + 1] = __half2float(__high2half(rmv[mt]));
    }
#pragma unroll
    for (int s = 0; s < 8; s++) {
#pragma unroll
        for (int off = 1; off <= 2; off <<= 1) {
            const float om = __shfl_xor_sync(0xFFFFFFFFu, rmf[s], off);
            const float os = __shfl_xor_sync(0xFFFFFFFFu, rs[s], off);
            const float nm = fmaxf(rmf[s], om);
            rs[s] = rs[s] * exp2f(rmf[s] - nm) + os * exp2f(om - nm);
            rmf[s] = nm;
        }
    }

    // ---- cross-warp reduce (2 warp_n groups) + store split partials ----
    float* redm = (float*)(smem + SRED_M);
    float* reds = (float*)(smem + SRED_S);
    if ((lane & 3) == 0) {
#pragma unroll
        for (int mt = 0; mt < 4; mt++)
#pragma unroll
            for (int h = 0; h < 2; h++) {
                const int row = warp_m * 64 + mt * 16 + h * 8 + (lane >> 2);
                redm[row * 2 + warp_n] = rmf[mt * 2 + h];
                reds[row * 2 + warp_n] = rs[mt * 2 + h];
            }
    }
    __syncthreads();
    if (tid < TM) {
        const float m0 = redm[tid * 2], m1 = redm[tid * 2 + 1];
        const float mg = fmaxf(m0, m1);
        const float sg = reds[tid * 2] * exp2f(m0 - mg) + reds[tid * 2 + 1] * exp2f(m1 - mg);
        g_pm[(rowBase + tid) * NSPLIT + split] = mg;
        g_ps[(rowBase + tid) * NSPLIT + split] = sg;
    }
    __syncthreads();            // block's stores issued before trigger
    pdl_launch_dependents();
}

// ---------------------------------------------------------------------------
// Combine (PDL secondary): pre-launches under main's tail; pdl_wait() gates
// the reads. 32 blocks reduce 256 rows each; last block sums 32 partials in
// fixed order (deterministic) and writes out.
// ---------------------------------------------------------------------------
__global__ void combine_kernel(float* __restrict__ out) {
    __shared__ float red[256];
    __shared__ bool amLast;
    pdl_wait();
    const int r = blockIdx.x * 256 + threadIdx.x;
    const float4 pm = *(const float4*)(g_pm + r * NSPLIT);
    const float4 ps = *(const float4*)(g_ps + r * NSPLIT);
    const float mg = fmaxf(fmaxf(pm.x, pm.y), fmaxf(pm.z, pm.w));
    const float sg = ps.x * exp2f(pm.x - mg) + ps.y * exp2f(pm.y - mg)
                   + ps.z * exp2f(pm.z - mg) + ps.w * exp2f(pm.w - mg);
    red[threadIdx.x] = LN2 * (mg + log2f(sg)) - g_pos[r];
    __syncthreads();
    for (int o = 128; o; o >>= 1) {
        if (threadIdx.x < o) red[threadIdx.x] += red[threadIdx.x + o];
        __syncthreads();
    }
    if (threadIdx.x == 0) {
        g_part[blockIdx.x] = red[0];
        __threadfence();
        const unsigned int t = atomicAdd(&g_ticket, 1u);
        amLast = (t == 31u);
    }
    __syncthreads();
    if (amLast && threadIdx.x == 0) {
        float tot = 0.0f;
#pragma unroll
        for (int i = 0; i < 32; i++) tot += g_part[i];
        out[0] = tot / (float)NN;
        g_ticket = 0u;   // reset for next graph replay
    }
}

// ---------------------------------------------------------------------------
extern "C" void kernel_launch(void* const* d_in, const int* in_sizes, int n_in,
                              void* d_out, int out_size) {
    const float* q = (const float*)d_in[0];
    const float* k = (const float*)d_in[1];
    float* out = (float*)d_out;

    cudaFuncSetAttribute(sim_lse_hmma_kernel,
                         cudaFuncAttributeMaxDynamicSharedMemorySize, SM_TOTAL);

    // 1) convert_k (plain launch)
    convert_k_kernel<<<NN * CC / 8 / 256, 256>>>(k);

    // 2) main GEMM as PDL secondary of convert_k
    {
        cudaLaunchConfig_t cfg = {};
        cfg.gridDim = dim3(NSPLIT, NN / TM, 1);
        cfg.blockDim = dim3(NTHREADS, 1, 1);
        cfg.dynamicSmemBytes = SM_TOTAL;
        cfg.stream = 0;
        cudaLaunchAttribute attr[1];
        attr[0].id = cudaLaunchAttributeProgrammaticStreamSerialization;
        attr[0].val.programmaticStreamSerializationAllowed = 1;
        cfg.attrs = attr;
        cfg.numAttrs = 1;
        cudaLaunchKernelEx(&cfg, sim_lse_hmma_kernel, q);
    }

    // 3) combine as PDL secondary of the main kernel
    {
        cudaLaunchConfig_t cfg = {};
        cfg.gridDim = dim3(32, 1, 1);
        cfg.blockDim = dim3(256, 1, 1);
        cfg.dynamicSmemBytes = 0;
        cfg.stream = 0;
        cudaLaunchAttribute attr[1];
        attr[0].id = cudaLaunchAttributeProgrammaticStreamSerialization;
        attr[0].val.programmaticStreamSerializationAllowed = 1;
        cfg.attrs = attr;
        cfg.numAttrs = 1;
        cudaLaunchKernelEx(&cfg, combine_kernel, out);
    }
}